// round 3
// baseline (speedup 1.0000x reference)
#include <cuda_runtime.h>

// LFR constants from the reference: M=7, N=6, LEFT=ceil((M-1)//2)=3, D=80.
#define MM 7
#define NN 6
#define LEFTP 3
#define DD 80
#define F4_PER_FRAME 20   /* 80/4  */
#define F4_PER_ROW   140  /* 7*20  */

#define MAXB 1024
__device__ int g_limit[MAXB];  // 3 + lens[b]
__device__ int g_fb[MAXB];     // fallback source frame for t >= limit

// One block, B threads (B <= 1024). Computes per-batch right_pad / T_all,
// reduces T_all_max across the batch, derives the fallback frame, and
// writes new_len (as float) if the output buffer carries it.
__global__ void lfr_prep_kernel(const int* __restrict__ lens,
                                float* __restrict__ newlen_out,
                                int T, int B, int write_newlen) {
    __shared__ int s_tall[MAXB];
    int b = threadIdx.x;
    int L = 1, T_all = 0;
    if (b < B) {
        L = lens[b];
        int c6    = (L + (NN - 1)) / NN;          // ceil(L/6)
        int delta = L + LEFTP + NN - NN * c6;     // L + 9 - 6*ceil(L/6)
        int rp    = MM - delta; if (rp < 0) rp = 0;
        T_all     = LEFTP + L + rp;
        if (write_newlen) newlen_out[b] = (float)(T_all / NN);
        g_limit[b] = LEFTP + L;
    }
    s_tall[b] = T_all;
    __syncthreads();
    for (int s = blockDim.x >> 1; s > 0; s >>= 1) {
        if (b < s) s_tall[b] = max(s_tall[b], s_tall[b + s]);
        __syncthreads();
    }
    int Tmax = s_tall[0];
    int jmax = Tmax - 1;  // padded index used for masked-out positions
    if (b < B) {
        // padded[j]: j<3 -> frame 0 ; 3<=j<3+T -> frame j-3 ; else -> frame L-1
        g_fb[b] = (jmax < LEFTP + T) ? (jmax - LEFTP) : (L - 1);
    }
}

// One float4 of output per thread. blockIdx.y = batch.
// out[b, f, m*80+d] = x[b, src(f*6+m), d]
__global__ void lfr_gather_kernel(const float4* __restrict__ x4,
                                  float4* __restrict__ out4,
                                  int T, int nf) {
    int b = blockIdx.y;
    int total = nf * F4_PER_ROW;
    int i = blockIdx.x * blockDim.x + threadIdx.x;
    if (i >= total) return;

    int limit = g_limit[b];
    int fb    = g_fb[b];

    int f = i / F4_PER_ROW;
    int r = i - f * F4_PER_ROW;
    int m = r / F4_PER_FRAME;
    int k = r - m * F4_PER_FRAME;

    int t   = f * NN + m;
    int tm3 = t - LEFTP;
    int src = (t < limit) ? (tm3 < 0 ? 0 : tm3) : fb;

    out4[(size_t)b * total + i] =
        x4[((size_t)b * T + src) * F4_PER_FRAME + k];
}

extern "C" void kernel_launch(void* const* d_in, const int* in_sizes, int n_in,
                              void* d_out, int out_size) {
    const float* x    = (const float*)d_in[0];
    const int*   lens = (const int*)d_in[1];

    int B = in_sizes[1];                 // 64
    int T = in_sizes[0] / (B * DD);      // 4096

    long long per = (long long)B * (MM * DD);  // elems per output frame-row across batch
    long long nf;
    int write_newlen = 0;
    if (out_size > B && ((long long)(out_size - B) % per) == 0) {
        write_newlen = 1;
        nf = ((long long)out_size - B) / per;
    } else {
        nf = (long long)out_size / per;
    }

    float* out    = (float*)d_out;
    float* newlen = out + (long long)B * nf * (MM * DD);

    lfr_prep_kernel<<<1, B>>>(lens, newlen, T, B, write_newlen);

    int total = (int)nf * F4_PER_ROW;
    dim3 grid((total + 255) / 256, B);
    lfr_gather_kernel<<<grid, 256>>>((const float4*)x, (float4*)out, T, (int)nf);
}